// round 15
// baseline (speedup 1.0000x reference)
#include <cuda_runtime.h>
#include <cuda_bf16.h>
#include <math.h>

#define Bsz 32
#define Rr  256
#define Tt  512
#define Cc  16
#define NC1 64
#define NC2 128

// ---- scratch (static __device__ per allocation rules) ----
__device__ __nv_bfloat16 g_zh[67108864];        // [B*C][R][T] bf16 hi of z
__device__ __nv_bfloat16 g_zl[67108864];        // bf16 lo of z
__device__ float g_epart[16777216];             // [32 sp][32 b][256 r][64 o]
__device__ float g_e[524288];                   // [B][R][C1]
__device__ float g_pooled[8192];                // [B][R]
__device__ float g_npart[262144];               // [64 splits][32 b][128 j]

__device__ __forceinline__ void fma2(unsigned long long &d,
                                     unsigned long long a,
                                     unsigned long long b) {
    asm("fma.rn.f32x2 %0, %1, %2, %0;" : "+l"(d) : "l"(a), "l"(b));
}
__device__ __forceinline__ unsigned smem_u32(const void* p) {
    return (unsigned)__cvta_generic_to_shared(p);
}
__device__ __forceinline__ void cp16(unsigned dst, const void* src) {
    asm volatile("cp.async.cg.shared.global [%0], [%1], 16;" :: "r"(dst), "l"(src));
}
#define CP_COMMIT() asm volatile("cp.async.commit_group;")
#define CP_WAIT0()  asm volatile("cp.async.wait_group 0;")
#define CP_WAIT1()  asm volatile("cp.async.wait_group 1;")

// bf16 2-way split of a float pair. hi word: [lo16]=bf16(a), [hi16]=bf16(b).
__device__ __forceinline__ void bf16_split2(float a, float b, unsigned &hi, unsigned &lo) {
    unsigned h;
    asm("cvt.rn.bf16x2.f32 %0, %1, %2;" : "=r"(h) : "f"(b), "f"(a));
    float ha = __uint_as_float(h << 16);
    float hb = __uint_as_float(h & 0xffff0000u);
    unsigned l;
    asm("cvt.rn.bf16x2.f32 %0, %1, %2;" : "=r"(l) : "f"(b - hb), "f"(a - ha));
    hi = h; lo = l;
}

// ---- warp-level tensor core (sm_80+ baseline; works on compute_103) ----
#define LDSM4(r, addr) \
    asm volatile("ldmatrix.sync.aligned.m8n8.x4.shared.b16 {%0,%1,%2,%3}, [%4];" \
        : "=r"((r)[0]), "=r"((r)[1]), "=r"((r)[2]), "=r"((r)[3]) : "r"(addr))

#define LDSM4T(r, addr) \
    asm volatile("ldmatrix.sync.aligned.m8n8.x4.trans.shared.b16 {%0,%1,%2,%3}, [%4];" \
        : "=r"((r)[0]), "=r"((r)[1]), "=r"((r)[2]), "=r"((r)[3]) : "r"(addr))

#define MMA16816(d, a, bp) \
    asm volatile("mma.sync.aligned.m16n8k16.row.col.f32.bf16.bf16.f32 " \
        "{%0,%1,%2,%3}, {%4,%5,%6,%7}, {%8,%9}, {%0,%1,%2,%3};" \
        : "+f"((d)[0]), "+f"((d)[1]), "+f"((d)[2]), "+f"((d)[3]) \
        : "r"((a)[0]), "r"((a)[1]), "r"((a)[2]), "r"((a)[3]), \
          "r"((bp)[0]), "r"((bp)[1]))

// ============================================================
// K1: per (b,r): stats + write z bf16 hi/lo [bc][r][t]
// ============================================================
__global__ void k_stats(const float* __restrict__ x) {
    int br = blockIdx.x;                 // b*R + r
    int b = br >> 8, r = br & 255;
    __shared__ __align__(16) float sx[Cc * 513];
    __shared__ float red[256];
    __shared__ float s_mean[Cc], s_inv[Cc];
    const float* xp = x + (size_t)br * (Tt * Cc);
    int tid = threadIdx.x;

    #pragma unroll
    for (int i = 0; i < 8; i++) {
        int idx4 = tid + i * 256;
        int t = idx4 >> 2;
        int c0 = (idx4 & 3) * 4;
        float4 v = *(const float4*)(xp + idx4 * 4);
        sx[(c0 + 0) * 513 + t] = v.x;
        sx[(c0 + 1) * 513 + t] = v.y;
        sx[(c0 + 2) * 513 + t] = v.z;
        sx[(c0 + 3) * 513 + t] = v.w;
    }
    __syncthreads();

    int c = tid & 15, seg = tid >> 4;
    float p = 0.f;
    #pragma unroll
    for (int u = 0; u < 32; u++) p += sx[c * 513 + seg * 32 + u];
    red[seg * 16 + c] = p;
    __syncthreads();
    if (tid < 16) {
        float s = 0.f;
        #pragma unroll
        for (int sg = 0; sg < 16; sg++) s += red[sg * 16 + tid];
        s_mean[tid] = s * (1.0f / Tt);
    }
    __syncthreads();

    float mc = s_mean[c];
    p = 0.f;
    #pragma unroll
    for (int u = 0; u < 32; u++) {
        float d = sx[c * 513 + seg * 32 + u] - mc;
        p += d * d;
    }
    red[seg * 16 + c] = p;
    __syncthreads();
    if (tid < 16) {
        float s = 0.f;
        #pragma unroll
        for (int sg = 0; sg < 16; sg++) s += red[sg * 16 + tid];
        s_inv[tid] = rsqrtf(s);
    }
    __syncthreads();

    int cw = tid >> 4;
    float m = s_mean[cw], inv = s_inv[cw];
    size_t zoff = (((size_t)b * Cc + cw) * Rr + r) * Tt;
    __nv_bfloat16* zh = g_zh + zoff;
    __nv_bfloat16* zl = g_zl + zoff;
    int q = tid & 15;
    #pragma unroll
    for (int j = 0; j < 8; j++) {
        int t = q * 4 + j * 64;
        float z0 = (sx[cw * 513 + t + 0] - m) * inv;
        float z1 = (sx[cw * 513 + t + 1] - m) * inv;
        float z2 = (sx[cw * 513 + t + 2] - m) * inv;
        float z3 = (sx[cw * 513 + t + 3] - m) * inv;
        unsigned h0, l0, h1, l1;
        bf16_split2(z0, z1, h0, l0);
        bf16_split2(z2, z3, h1, l1);
        uint2 hv; hv.x = h0; hv.y = h1;
        uint2 lv; lv.x = l0; lv.y = l1;
        *(uint2*)(zh + t) = hv;
        *(uint2*)(zl + t) = lv;
    }
}

// ============================================================
// K2 (fused HMMA): per (b,c,tc) CTA — one 256-t chunk each.
//  Phase 1: y[64][256] = W * z  -> SMEM (h/l split)
//  Phase 2: epart[r][o] += z * y^T  (32-way split-K: sp = c*2+tc)
// ============================================================
#define YWS  264
#define YROW 528
#define FSM_WH 0
#define FSM_WL 33792
#define FSM_YH 67584
#define FSM_YL 101376
#define FSM_Z  135168
#define FSM_TOTAL 217088

__global__ __launch_bounds__(256, 1) void k_fused(const float* __restrict__ W_edge) {
    extern __shared__ __align__(16) char fsm[];
    unsigned base = smem_u32(fsm);
    int tid = threadIdx.x;
    int wid = tid >> 5, lane = tid & 31;
    int bidx = blockIdx.x;                // 0..1023
    int bc = bidx >> 1, tcx = bidx & 1;
    int b = bc >> 4, c = bc & 15;
    int tbase = tcx * 256;
    int mw = wid & 1, nw = wid >> 1;

    // ---- prologue: split W[:,c,:] fp32 -> bf16 hi/lo in smem ----
    {
        __nv_bfloat16* Wh = (__nv_bfloat16*)(fsm + FSM_WH);
        __nv_bfloat16* Wl = (__nv_bfloat16*)(fsm + FSM_WL);
        int wo = tid >> 2, wrs = (tid & 3) * 64;
        const float* wrow = W_edge + (size_t)wo * (Cc * Rr) + (size_t)c * Rr + wrs;
        #pragma unroll
        for (int j = 0; j < 32; j++) {
            float2 v = *(const float2*)(wrow + j * 2);
            unsigned h, l;
            bf16_split2(v.x, v.y, h, l);
            *(unsigned*)(Wh + wo * YWS + wrs + j * 2) = h;
            *(unsigned*)(Wl + wo * YWS + wrs + j * 2) = l;
        }
    }

    const __nv_bfloat16* zh0 = g_zh + (size_t)bc * Rr * Tt;
    const __nv_bfloat16* zl0 = g_zl + (size_t)bc * Rr * Tt;

    int matq = lane >> 3, qr = lane & 7;

    unsigned p1_aoff = (unsigned)(((matq & 1) * 8 + qr) * YROW + (matq >> 1) * 16);
    unsigned awh = base + FSM_WH + (unsigned)(mw * 32) * YROW + p1_aoff;
    unsigned awl = base + FSM_WL + (unsigned)(mw * 32) * YROW + p1_aoff;
    unsigned p1_boff = (unsigned)(((matq & 1) * 8 + qr) * YROW + (nw * 64 + (matq >> 1) * 8) * 2);
    unsigned p2_arow = (unsigned)(((matq & 1) * 8 + qr) * 80 + (matq >> 1) * 16);
    unsigned p2_brow = (unsigned)(((matq >> 1) * 8 + qr) * YROW + (matq & 1) * 16);

    float acc2[2][8][4];
    #pragma unroll
    for (int mt = 0; mt < 2; mt++)
        #pragma unroll
        for (int nt = 0; nt < 8; nt++)
            #pragma unroll
            for (int u = 0; u < 4; u++) acc2[mt][nt][u] = 0.f;

    // ================= PHASE 1: y = W * z =================
    auto zfill1 = [&](int kb, int buf) {
        unsigned dh = base + FSM_Z + (unsigned)buf * 33792u;
        unsigned dl = dh + 16896u;
        #pragma unroll
        for (int i = 0; i < 4; i++) {
            int idx = tid + i * 256;
            int row = idx >> 5, seg = idx & 31;
            unsigned doff = (unsigned)(row * YWS + seg * 8) * 2;
            size_t soff = (size_t)(kb * 32 + row) * Tt + tbase + seg * 8;
            cp16(dh + doff, zh0 + soff);
            cp16(dl + doff, zl0 + soff);
        }
        CP_COMMIT();
    };

    float acc1[2][8][4];
    #pragma unroll
    for (int mt = 0; mt < 2; mt++)
        #pragma unroll
        for (int nt = 0; nt < 8; nt++)
            #pragma unroll
            for (int u = 0; u < 4; u++) acc1[mt][nt][u] = 0.f;

    zfill1(0, 0);
    for (int kb = 0; kb < 8; kb++) {
        __syncthreads();
        if (kb + 1 < 8) { zfill1(kb + 1, (kb + 1) & 1); CP_WAIT1(); }
        else CP_WAIT0();
        __syncthreads();

        unsigned zh_b = base + FSM_Z + (unsigned)(kb & 1) * 33792u + p1_boff;
        unsigned zl_b = zh_b + 16896u;
        #pragma unroll
        for (int k0 = 0; k0 < 2; k0++) {
            unsigned akoff = (unsigned)(kb * 32 + k0 * 16) * 2;
            unsigned ah[2][4], al[2][4];
            LDSM4(ah[0], awh + akoff);
            LDSM4(ah[1], awh + (unsigned)(16 * YROW) + akoff);
            LDSM4(al[0], awl + akoff);
            LDSM4(al[1], awl + (unsigned)(16 * YROW) + akoff);
            unsigned zrow = (unsigned)(k0 * 16) * YROW;
            unsigned bh4[4][4], bl4[4][4];
            #pragma unroll
            for (int i = 0; i < 4; i++) {
                LDSM4T(bh4[i], zh_b + zrow + (unsigned)(i * 16) * 2);
                LDSM4T(bl4[i], zl_b + zrow + (unsigned)(i * 16) * 2);
            }
            #pragma unroll
            for (int mt = 0; mt < 2; mt++)
                #pragma unroll
                for (int i = 0; i < 4; i++)
                    #pragma unroll
                    for (int h = 0; h < 2; h++)
                        MMA16816(acc1[mt][i * 2 + h], ah[mt], &bh4[i][h * 2]);
            #pragma unroll
            for (int mt = 0; mt < 2; mt++)
                #pragma unroll
                for (int i = 0; i < 4; i++)
                    #pragma unroll
                    for (int h = 0; h < 2; h++)
                        MMA16816(acc1[mt][i * 2 + h], ah[mt], &bl4[i][h * 2]);
            #pragma unroll
            for (int mt = 0; mt < 2; mt++)
                #pragma unroll
                for (int i = 0; i < 4; i++)
                    #pragma unroll
                    for (int h = 0; h < 2; h++)
                        MMA16816(acc1[mt][i * 2 + h], al[mt], &bh4[i][h * 2]);
        }
    }

    // write y (bf16 h/l split) into smem [o][264]
    {
        int g = lane >> 2, tq = lane & 3;
        #pragma unroll
        for (int mt = 0; mt < 2; mt++) {
            #pragma unroll
            for (int nt = 0; nt < 8; nt++) {
                int o = mw * 32 + mt * 16 + g;
                int t = nw * 64 + nt * 8 + tq * 2;
                unsigned h0, l0, h1, l1;
                bf16_split2(acc1[mt][nt][0], acc1[mt][nt][1], h0, l0);
                bf16_split2(acc1[mt][nt][2], acc1[mt][nt][3], h1, l1);
                *(unsigned*)(fsm + FSM_YH + o * YROW + t * 2) = h0;
                *(unsigned*)(fsm + FSM_YL + o * YROW + t * 2) = l0;
                *(unsigned*)(fsm + FSM_YH + (o + 8) * YROW + t * 2) = h1;
                *(unsigned*)(fsm + FSM_YL + (o + 8) * YROW + t * 2) = l1;
            }
        }
    }
    __syncthreads();

    // ================= PHASE 2: epart += z * y^T =================
    auto zfill2 = [&](int ch, int buf) {
        unsigned dh = base + FSM_Z + (unsigned)buf * 40960u;
        unsigned dl = dh + 20480u;
        int r = tid;
        size_t soff = (size_t)r * Tt + tbase + ch * 32;
        #pragma unroll
        for (int j = 0; j < 4; j++) {
            cp16(dh + (unsigned)(r * 80 + j * 16), zh0 + soff + j * 8);
            cp16(dl + (unsigned)(r * 80 + j * 16), zl0 + soff + j * 8);
        }
        CP_COMMIT();
    };

    zfill2(0, 0);
    for (int ch = 0; ch < 8; ch++) {
        __syncthreads();
        if (ch + 1 < 8) { zfill2(ch + 1, (ch + 1) & 1); CP_WAIT1(); }
        else CP_WAIT0();
        __syncthreads();

        unsigned Ah = base + FSM_Z + (unsigned)(ch & 1) * 40960u
                    + (unsigned)(wid * 32) * 80 + p2_arow;
        unsigned Al = Ah + 20480u;
        unsigned Bh = base + FSM_YH + p2_brow + (unsigned)(ch * 64);
        unsigned Bl = base + FSM_YL + p2_brow + (unsigned)(ch * 64);

        #pragma unroll
        for (int k0 = 0; k0 < 2; k0++) {
            unsigned koff = (unsigned)(k0 * 32);
            unsigned ah[2][4], al[2][4];
            LDSM4(ah[0], Ah + koff);
            LDSM4(ah[1], Ah + 16 * 80 + koff);
            LDSM4(al[0], Al + koff);
            LDSM4(al[1], Al + 16 * 80 + koff);
            unsigned bh[4][4], bl[4][4];
            #pragma unroll
            for (int i = 0; i < 4; i++) {
                LDSM4(bh[i], Bh + (unsigned)(i * 16) * YROW + koff);
                LDSM4(bl[i], Bl + (unsigned)(i * 16) * YROW + koff);
            }
            #pragma unroll
            for (int mt = 0; mt < 2; mt++)
                #pragma unroll
                for (int i = 0; i < 4; i++)
                    #pragma unroll
                    for (int h = 0; h < 2; h++)
                        MMA16816(acc2[mt][i * 2 + h], ah[mt], &bh[i][h * 2]);
            #pragma unroll
            for (int mt = 0; mt < 2; mt++)
                #pragma unroll
                for (int i = 0; i < 4; i++)
                    #pragma unroll
                    for (int h = 0; h < 2; h++)
                        MMA16816(acc2[mt][i * 2 + h], ah[mt], &bl[i][h * 2]);
            #pragma unroll
            for (int mt = 0; mt < 2; mt++)
                #pragma unroll
                for (int i = 0; i < 4; i++)
                    #pragma unroll
                    for (int h = 0; h < 2; h++)
                        MMA16816(acc2[mt][i * 2 + h], al[mt], &bh[i][h * 2]);
        }
    }

    // epilogue: write split-K partials (32-way: sp = c*2 + tcx)
    int g = lane >> 2, tq = lane & 3;
    float* ep = g_epart + (((size_t)(c * 2 + tcx)) * Bsz + b) * Rr * NC1;
    #pragma unroll
    for (int mt = 0; mt < 2; mt++) {
        #pragma unroll
        for (int nt = 0; nt < 8; nt++) {
            int r = wid * 32 + mt * 16 + g;
            int o = nt * 8 + tq * 2;
            *(float2*)(ep + (size_t)r * NC1 + o) = make_float2(acc2[mt][nt][0], acc2[mt][nt][1]);
            *(float2*)(ep + (size_t)(r + 8) * NC1 + o) = make_float2(acc2[mt][nt][2], acc2[mt][nt][3]);
        }
    }
}

// ============================================================
// K3: sum 32 split-K partials, bias + leaky_relu -> e; pooled
// ============================================================
__global__ void k_reduce(const float* __restrict__ b_edge) {
    int br = blockIdx.x;                  // b*R + r
    int b = br >> 8, r = br & 255;
    int o = threadIdx.x;                  // 0..63
    float s = 0.f;
    #pragma unroll 8
    for (int cg = 0; cg < 32; cg++)
        s += g_epart[(((size_t)cg * Bsz + b) * Rr + r) * NC1 + o];
    s += b_edge[o];
    s = (s > 0.f) ? s : 0.01f * s;
    g_e[((size_t)b * Rr + r) * NC1 + o] = s;

    float v = s;
    #pragma unroll
    for (int off = 16; off > 0; off >>= 1) v += __shfl_down_sync(0xffffffffu, v, off);
    __shared__ float w2[2];
    if ((o & 31) == 0) w2[o >> 5] = v;
    __syncthreads();
    if (o == 0) g_pooled[b * Rr + r] = (w2[0] + w2[1]) * (1.0f / 64.0f);
}

// ============================================================
// K4: NodeConv split-K with inlined attention MLP.
// 64 blocks, each owns 4 r's; each block recomputes att for all 32 b
// (tiny MLP, W1/W2 L2-resident) and writes att out rows it owns.
// ============================================================
__global__ __launch_bounds__(256) void k_node(const float* __restrict__ W_node,
                                              const float* __restrict__ W1,
                                              const float* __restrict__ b1,
                                              const float* __restrict__ W2,
                                              const float* __restrict__ b2,
                                              float* __restrict__ out) {
    __shared__ __align__(16) float sae[32 * 256];   // first pooled[32][256], then [b][o][rr]
    __shared__ __align__(16) float s_h[32 * 64];
    __shared__ float s_att[128];
    int blk = blockIdx.x;
    int r0 = blk * 4;
    int tid = threadIdx.x;

    // ---- load pooled [32 b][256 r] into sae ----
    #pragma unroll
    for (int i = 0; i < 8; i++) {
        int idx = tid + i * 256;          // 0..2047 float4s (8192 floats)
        ((float4*)sae)[idx] = ((const float4*)g_pooled)[idx];
    }
    __syncthreads();

    // ---- layer 1: h[b][hi] = relu(b1 + W1 @ pooled[b]) ----
    #pragma unroll
    for (int i = 0; i < 8; i++) {
        int task = tid + i * 256;         // 0..2047 = 32b x 64hi
        int bb = task >> 6, hi = task & 63;
        const float* w = W1 + hi * 256;
        const float* pv = sae + bb * 256;
        float a = b1[hi];
        #pragma unroll 8
        for (int j = 0; j < 64; j++) {
            float4 wv = *(const float4*)(w + j * 4);
            float4 p4 = *(const float4*)(pv + j * 4);
            a += wv.x * p4.x + wv.y * p4.y + wv.z * p4.z + wv.w * p4.w;
        }
        s_h[bb * 64 + hi] = a > 0.f ? a : 0.f;
    }
    __syncthreads();

    // ---- layer 2 + sigmoid for the 4 owned r's, all b ----
    if (tid < 128) {
        int bb = tid >> 2, rr = tid & 3;
        const float* w = W2 + (r0 + rr) * 64;
        const float* hv = s_h + bb * 64;
        float a = b2[r0 + rr];
        #pragma unroll
        for (int j = 0; j < 16; j++) {
            float4 wv = *(const float4*)(w + j * 4);
            float4 h4 = *(const float4*)(hv + j * 4);
            a += wv.x * h4.x + wv.y * h4.y + wv.z * h4.z + wv.w * h4.w;
        }
        float att = 1.0f / (1.0f + expf(-a));
        s_att[tid] = att;
        out[Bsz * NC2 + bb * Rr + r0 + rr] = att;
    }
    __syncthreads();

    // ---- fill sae[b][o][rr] = e * att (overwrites pooled) ----
    #pragma unroll
    for (int i = 0; i < 8; i++) {
        int idx4 = tid + i * 256;
        int b = idx4 >> 6, rr = (idx4 >> 4) & 3, o4 = idx4 & 15;
        float4 v = *(const float4*)(g_e + ((size_t)(b * Rr) + r0 + rr) * NC1 + o4 * 4);
        float a = s_att[b * 4 + rr];
        sae[b * 256 + (o4 * 4 + 0) * 4 + rr] = v.x * a;
        sae[b * 256 + (o4 * 4 + 1) * 4 + rr] = v.y * a;
        sae[b * 256 + (o4 * 4 + 2) * 4 + rr] = v.z * a;
        sae[b * 256 + (o4 * 4 + 3) * 4 + rr] = v.w * a;
    }
    __syncthreads();

    int j = tid >> 1, bh = tid & 1;
    unsigned long long acc2[16];
    #pragma unroll
    for (int i = 0; i < 16; i++) acc2[i] = 0ull;

    const float* wj = W_node + (size_t)j * (NC1 * Rr) + r0;
    #pragma unroll 4
    for (int o = 0; o < 64; o++) {
        ulonglong2 w = *(const ulonglong2*)(wj + o * Rr);
        const float* bsp = sae + bh * 16 * 256 + o * 4;
        #pragma unroll
        for (int bi = 0; bi < 16; bi++) {
            ulonglong2 ae = *(const ulonglong2*)(bsp + bi * 256);
            fma2(acc2[bi], w.x, ae.x);
            fma2(acc2[bi], w.y, ae.y);
        }
    }

    #pragma unroll
    for (int bi = 0; bi < 16; bi++) {
        float2 p = *(float2*)&acc2[bi];
        int b = bh * 16 + bi;
        g_npart[((size_t)blk * 32 + b) * NC2 + j] = p.x + p.y;
    }
}

// ============================================================
// K5: reduce 64 split-K partials, bias + leaky_relu -> out
// ============================================================
__global__ void k_nred(const float* __restrict__ b_node, float* __restrict__ out) {
    int b = blockIdx.x, j = threadIdx.x;
    float s = 0.f;
    #pragma unroll 8
    for (int sp = 0; sp < 64; sp++)
        s += g_npart[((size_t)sp * 32 + b) * NC2 + j];
    s += b_node[j];
    out[b * NC2 + j] = s > 0.f ? s : 0.01f * s;
}

// ============================================================
extern "C" void kernel_launch(void* const* d_in, const int* in_sizes, int n_in,
                              void* d_out, int out_size) {
    const float* x      = (const float*)d_in[0];
    const float* W_edge = (const float*)d_in[1];
    const float* b_edge = (const float*)d_in[2];
    const float* W1     = (const float*)d_in[3];
    const float* b1     = (const float*)d_in[4];
    const float* W2     = (const float*)d_in[5];
    const float* b2     = (const float*)d_in[6];
    const float* W_node = (const float*)d_in[7];
    const float* b_node = (const float*)d_in[8];
    float* out = (float*)d_out;

    cudaFuncSetAttribute(k_fused, cudaFuncAttributeMaxDynamicSharedMemorySize, FSM_TOTAL);

    k_stats <<<Bsz * Rr, 256>>>(x);
    k_fused <<<Bsz * Cc * 2, 256, FSM_TOTAL>>>(W_edge);
    k_reduce<<<Bsz * Rr, 64>>>(b_edge);
    k_node  <<<64, 256>>>(W_node, W1, b1, W2, b2, out);
    k_nred  <<<Bsz, 128>>>(b_node, out);
}

// round 16
// speedup vs baseline: 1.1787x; 1.1787x over previous
#include <cuda_runtime.h>
#include <cuda_bf16.h>
#include <math.h>

#define Bsz 32
#define Rr  256
#define Tt  512
#define Cc  16
#define NC1 64
#define NC2 128

// ---- scratch (static __device__ per allocation rules) ----
__device__ __nv_bfloat16 g_zh[67108864];        // [B*C][R][T] bf16 hi of z
__device__ __nv_bfloat16 g_zl[67108864];        // bf16 lo of z
__device__ float g_epart[16777216];             // [32 sp][32 b][256 r][64 o]
__device__ float g_e[524288];                   // [B][R][C1]
__device__ float g_pooled[8192];                // [B][R]
__device__ float g_att[8192];                   // [B][R]
__device__ float g_npart[262144];               // [64 splits][32 b][128 j]

__device__ __forceinline__ void fma2(unsigned long long &d,
                                     unsigned long long a,
                                     unsigned long long b) {
    asm("fma.rn.f32x2 %0, %1, %2, %0;" : "+l"(d) : "l"(a), "l"(b));
}
__device__ __forceinline__ unsigned smem_u32(const void* p) {
    return (unsigned)__cvta_generic_to_shared(p);
}
__device__ __forceinline__ void cp16(unsigned dst, const void* src) {
    asm volatile("cp.async.cg.shared.global [%0], [%1], 16;" :: "r"(dst), "l"(src));
}
#define CP_COMMIT() asm volatile("cp.async.commit_group;")
#define CP_WAIT0()  asm volatile("cp.async.wait_group 0;")
#define CP_WAIT1()  asm volatile("cp.async.wait_group 1;")

// bf16 2-way split of a float pair. hi word: [lo16]=bf16(a), [hi16]=bf16(b).
__device__ __forceinline__ void bf16_split2(float a, float b, unsigned &hi, unsigned &lo) {
    unsigned h;
    asm("cvt.rn.bf16x2.f32 %0, %1, %2;" : "=r"(h) : "f"(b), "f"(a));
    float ha = __uint_as_float(h << 16);
    float hb = __uint_as_float(h & 0xffff0000u);
    unsigned l;
    asm("cvt.rn.bf16x2.f32 %0, %1, %2;" : "=r"(l) : "f"(b - hb), "f"(a - ha));
    hi = h; lo = l;
}

// ---- warp-level tensor core (sm_80+ baseline; works on compute_103) ----
#define LDSM4(r, addr) \
    asm volatile("ldmatrix.sync.aligned.m8n8.x4.shared.b16 {%0,%1,%2,%3}, [%4];" \
        : "=r"((r)[0]), "=r"((r)[1]), "=r"((r)[2]), "=r"((r)[3]) : "r"(addr))

#define LDSM4T(r, addr) \
    asm volatile("ldmatrix.sync.aligned.m8n8.x4.trans.shared.b16 {%0,%1,%2,%3}, [%4];" \
        : "=r"((r)[0]), "=r"((r)[1]), "=r"((r)[2]), "=r"((r)[3]) : "r"(addr))

#define MMA16816(d, a, bp) \
    asm volatile("mma.sync.aligned.m16n8k16.row.col.f32.bf16.bf16.f32 " \
        "{%0,%1,%2,%3}, {%4,%5,%6,%7}, {%8,%9}, {%0,%1,%2,%3};" \
        : "+f"((d)[0]), "+f"((d)[1]), "+f"((d)[2]), "+f"((d)[3]) \
        : "r"((a)[0]), "r"((a)[1]), "r"((a)[2]), "r"((a)[3]), \
          "r"((bp)[0]), "r"((bp)[1]))

// ============================================================
// K1: per (b,r): stats + write z bf16 hi/lo [bc][r][t]
// ============================================================
__global__ void k_stats(const float* __restrict__ x) {
    int br = blockIdx.x;                 // b*R + r
    int b = br >> 8, r = br & 255;
    __shared__ __align__(16) float sx[Cc * 513];
    __shared__ float red[256];
    __shared__ float s_mean[Cc], s_inv[Cc];
    const float* xp = x + (size_t)br * (Tt * Cc);
    int tid = threadIdx.x;

    #pragma unroll
    for (int i = 0; i < 8; i++) {
        int idx4 = tid + i * 256;
        int t = idx4 >> 2;
        int c0 = (idx4 & 3) * 4;
        float4 v = *(const float4*)(xp + idx4 * 4);
        sx[(c0 + 0) * 513 + t] = v.x;
        sx[(c0 + 1) * 513 + t] = v.y;
        sx[(c0 + 2) * 513 + t] = v.z;
        sx[(c0 + 3) * 513 + t] = v.w;
    }
    __syncthreads();

    int c = tid & 15, seg = tid >> 4;
    float p = 0.f;
    #pragma unroll
    for (int u = 0; u < 32; u++) p += sx[c * 513 + seg * 32 + u];
    red[seg * 16 + c] = p;
    __syncthreads();
    if (tid < 16) {
        float s = 0.f;
        #pragma unroll
        for (int sg = 0; sg < 16; sg++) s += red[sg * 16 + tid];
        s_mean[tid] = s * (1.0f / Tt);
    }
    __syncthreads();

    float mc = s_mean[c];
    p = 0.f;
    #pragma unroll
    for (int u = 0; u < 32; u++) {
        float d = sx[c * 513 + seg * 32 + u] - mc;
        p += d * d;
    }
    red[seg * 16 + c] = p;
    __syncthreads();
    if (tid < 16) {
        float s = 0.f;
        #pragma unroll
        for (int sg = 0; sg < 16; sg++) s += red[sg * 16 + tid];
        s_inv[tid] = rsqrtf(s);
    }
    __syncthreads();

    int cw = tid >> 4;
    float m = s_mean[cw], inv = s_inv[cw];
    size_t zoff = (((size_t)b * Cc + cw) * Rr + r) * Tt;
    __nv_bfloat16* zh = g_zh + zoff;
    __nv_bfloat16* zl = g_zl + zoff;
    int q = tid & 15;
    #pragma unroll
    for (int j = 0; j < 8; j++) {
        int t = q * 4 + j * 64;
        float z0 = (sx[cw * 513 + t + 0] - m) * inv;
        float z1 = (sx[cw * 513 + t + 1] - m) * inv;
        float z2 = (sx[cw * 513 + t + 2] - m) * inv;
        float z3 = (sx[cw * 513 + t + 3] - m) * inv;
        unsigned h0, l0, h1, l1;
        bf16_split2(z0, z1, h0, l0);
        bf16_split2(z2, z3, h1, l1);
        uint2 hv; hv.x = h0; hv.y = h1;
        uint2 lv; lv.x = l0; lv.y = l1;
        *(uint2*)(zh + t) = hv;
        *(uint2*)(zl + t) = lv;
    }
}

// ============================================================
// K2 (fused HMMA): per (b,c,tc) CTA — one 256-t chunk each.
//  Phase 1: y[64][256] = W * z  -> SMEM (h/l split)
//  Phase 2: epart[r][o] += z * y^T  (32-way split-K: sp = c*2+tc)
// ============================================================
#define YWS  264
#define YROW 528
#define FSM_WH 0
#define FSM_WL 33792
#define FSM_YH 67584
#define FSM_YL 101376
#define FSM_Z  135168
#define FSM_TOTAL 217088

__global__ __launch_bounds__(256, 1) void k_fused(const float* __restrict__ W_edge) {
    extern __shared__ __align__(16) char fsm[];
    unsigned base = smem_u32(fsm);
    int tid = threadIdx.x;
    int wid = tid >> 5, lane = tid & 31;
    int bidx = blockIdx.x;                // 0..1023
    int bc = bidx >> 1, tcx = bidx & 1;
    int b = bc >> 4, c = bc & 15;
    int tbase = tcx * 256;
    int mw = wid & 1, nw = wid >> 1;

    // ---- prologue: split W[:,c,:] fp32 -> bf16 hi/lo in smem ----
    {
        __nv_bfloat16* Wh = (__nv_bfloat16*)(fsm + FSM_WH);
        __nv_bfloat16* Wl = (__nv_bfloat16*)(fsm + FSM_WL);
        int wo = tid >> 2, wrs = (tid & 3) * 64;
        const float* wrow = W_edge + (size_t)wo * (Cc * Rr) + (size_t)c * Rr + wrs;
        #pragma unroll
        for (int j = 0; j < 32; j++) {
            float2 v = *(const float2*)(wrow + j * 2);
            unsigned h, l;
            bf16_split2(v.x, v.y, h, l);
            *(unsigned*)(Wh + wo * YWS + wrs + j * 2) = h;
            *(unsigned*)(Wl + wo * YWS + wrs + j * 2) = l;
        }
    }

    const __nv_bfloat16* zh0 = g_zh + (size_t)bc * Rr * Tt;
    const __nv_bfloat16* zl0 = g_zl + (size_t)bc * Rr * Tt;

    int matq = lane >> 3, qr = lane & 7;

    unsigned p1_aoff = (unsigned)(((matq & 1) * 8 + qr) * YROW + (matq >> 1) * 16);
    unsigned awh = base + FSM_WH + (unsigned)(mw * 32) * YROW + p1_aoff;
    unsigned awl = base + FSM_WL + (unsigned)(mw * 32) * YROW + p1_aoff;
    unsigned p1_boff = (unsigned)(((matq & 1) * 8 + qr) * YROW + (nw * 64 + (matq >> 1) * 8) * 2);
    unsigned p2_arow = (unsigned)(((matq & 1) * 8 + qr) * 80 + (matq >> 1) * 16);
    unsigned p2_brow = (unsigned)(((matq >> 1) * 8 + qr) * YROW + (matq & 1) * 16);

    float acc2[2][8][4];
    #pragma unroll
    for (int mt = 0; mt < 2; mt++)
        #pragma unroll
        for (int nt = 0; nt < 8; nt++)
            #pragma unroll
            for (int u = 0; u < 4; u++) acc2[mt][nt][u] = 0.f;

    // ================= PHASE 1: y = W * z =================
    auto zfill1 = [&](int kb, int buf) {
        unsigned dh = base + FSM_Z + (unsigned)buf * 33792u;
        unsigned dl = dh + 16896u;
        #pragma unroll
        for (int i = 0; i < 4; i++) {
            int idx = tid + i * 256;
            int row = idx >> 5, seg = idx & 31;
            unsigned doff = (unsigned)(row * YWS + seg * 8) * 2;
            size_t soff = (size_t)(kb * 32 + row) * Tt + tbase + seg * 8;
            cp16(dh + doff, zh0 + soff);
            cp16(dl + doff, zl0 + soff);
        }
        CP_COMMIT();
    };

    float acc1[2][8][4];
    #pragma unroll
    for (int mt = 0; mt < 2; mt++)
        #pragma unroll
        for (int nt = 0; nt < 8; nt++)
            #pragma unroll
            for (int u = 0; u < 4; u++) acc1[mt][nt][u] = 0.f;

    zfill1(0, 0);
    for (int kb = 0; kb < 8; kb++) {
        __syncthreads();
        if (kb + 1 < 8) { zfill1(kb + 1, (kb + 1) & 1); CP_WAIT1(); }
        else CP_WAIT0();
        __syncthreads();

        unsigned zh_b = base + FSM_Z + (unsigned)(kb & 1) * 33792u + p1_boff;
        unsigned zl_b = zh_b + 16896u;
        #pragma unroll
        for (int k0 = 0; k0 < 2; k0++) {
            unsigned akoff = (unsigned)(kb * 32 + k0 * 16) * 2;
            unsigned ah[2][4], al[2][4];
            LDSM4(ah[0], awh + akoff);
            LDSM4(ah[1], awh + (unsigned)(16 * YROW) + akoff);
            LDSM4(al[0], awl + akoff);
            LDSM4(al[1], awl + (unsigned)(16 * YROW) + akoff);
            unsigned zrow = (unsigned)(k0 * 16) * YROW;
            unsigned bh4[4][4], bl4[4][4];
            #pragma unroll
            for (int i = 0; i < 4; i++) {
                LDSM4T(bh4[i], zh_b + zrow + (unsigned)(i * 16) * 2);
                LDSM4T(bl4[i], zl_b + zrow + (unsigned)(i * 16) * 2);
            }
            #pragma unroll
            for (int mt = 0; mt < 2; mt++)
                #pragma unroll
                for (int i = 0; i < 4; i++)
                    #pragma unroll
                    for (int h = 0; h < 2; h++)
                        MMA16816(acc1[mt][i * 2 + h], ah[mt], &bh4[i][h * 2]);
            #pragma unroll
            for (int mt = 0; mt < 2; mt++)
                #pragma unroll
                for (int i = 0; i < 4; i++)
                    #pragma unroll
                    for (int h = 0; h < 2; h++)
                        MMA16816(acc1[mt][i * 2 + h], ah[mt], &bl4[i][h * 2]);
            #pragma unroll
            for (int mt = 0; mt < 2; mt++)
                #pragma unroll
                for (int i = 0; i < 4; i++)
                    #pragma unroll
                    for (int h = 0; h < 2; h++)
                        MMA16816(acc1[mt][i * 2 + h], al[mt], &bh4[i][h * 2]);
        }
    }

    // write y (bf16 h/l split) into smem [o][264]
    {
        int g = lane >> 2, tq = lane & 3;
        #pragma unroll
        for (int mt = 0; mt < 2; mt++) {
            #pragma unroll
            for (int nt = 0; nt < 8; nt++) {
                int o = mw * 32 + mt * 16 + g;
                int t = nw * 64 + nt * 8 + tq * 2;
                unsigned h0, l0, h1, l1;
                bf16_split2(acc1[mt][nt][0], acc1[mt][nt][1], h0, l0);
                bf16_split2(acc1[mt][nt][2], acc1[mt][nt][3], h1, l1);
                *(unsigned*)(fsm + FSM_YH + o * YROW + t * 2) = h0;
                *(unsigned*)(fsm + FSM_YL + o * YROW + t * 2) = l0;
                *(unsigned*)(fsm + FSM_YH + (o + 8) * YROW + t * 2) = h1;
                *(unsigned*)(fsm + FSM_YL + (o + 8) * YROW + t * 2) = l1;
            }
        }
    }
    __syncthreads();

    // ================= PHASE 2: epart += z * y^T =================
    auto zfill2 = [&](int ch, int buf) {
        unsigned dh = base + FSM_Z + (unsigned)buf * 40960u;
        unsigned dl = dh + 20480u;
        int r = tid;
        size_t soff = (size_t)r * Tt + tbase + ch * 32;
        #pragma unroll
        for (int j = 0; j < 4; j++) {
            cp16(dh + (unsigned)(r * 80 + j * 16), zh0 + soff + j * 8);
            cp16(dl + (unsigned)(r * 80 + j * 16), zl0 + soff + j * 8);
        }
        CP_COMMIT();
    };

    zfill2(0, 0);
    for (int ch = 0; ch < 8; ch++) {
        __syncthreads();
        if (ch + 1 < 8) { zfill2(ch + 1, (ch + 1) & 1); CP_WAIT1(); }
        else CP_WAIT0();
        __syncthreads();

        unsigned Ah = base + FSM_Z + (unsigned)(ch & 1) * 40960u
                    + (unsigned)(wid * 32) * 80 + p2_arow;
        unsigned Al = Ah + 20480u;
        unsigned Bh = base + FSM_YH + p2_brow + (unsigned)(ch * 64);
        unsigned Bl = base + FSM_YL + p2_brow + (unsigned)(ch * 64);

        #pragma unroll
        for (int k0 = 0; k0 < 2; k0++) {
            unsigned koff = (unsigned)(k0 * 32);
            unsigned ah[2][4], al[2][4];
            LDSM4(ah[0], Ah + koff);
            LDSM4(ah[1], Ah + 16 * 80 + koff);
            LDSM4(al[0], Al + koff);
            LDSM4(al[1], Al + 16 * 80 + koff);
            unsigned bh[4][4], bl[4][4];
            #pragma unroll
            for (int i = 0; i < 4; i++) {
                LDSM4(bh[i], Bh + (unsigned)(i * 16) * YROW + koff);
                LDSM4(bl[i], Bl + (unsigned)(i * 16) * YROW + koff);
            }
            #pragma unroll
            for (int mt = 0; mt < 2; mt++)
                #pragma unroll
                for (int i = 0; i < 4; i++)
                    #pragma unroll
                    for (int h = 0; h < 2; h++)
                        MMA16816(acc2[mt][i * 2 + h], ah[mt], &bh[i][h * 2]);
            #pragma unroll
            for (int mt = 0; mt < 2; mt++)
                #pragma unroll
                for (int i = 0; i < 4; i++)
                    #pragma unroll
                    for (int h = 0; h < 2; h++)
                        MMA16816(acc2[mt][i * 2 + h], ah[mt], &bl[i][h * 2]);
            #pragma unroll
            for (int mt = 0; mt < 2; mt++)
                #pragma unroll
                for (int i = 0; i < 4; i++)
                    #pragma unroll
                    for (int h = 0; h < 2; h++)
                        MMA16816(acc2[mt][i * 2 + h], al[mt], &bh[i][h * 2]);
        }
    }

    // epilogue: write split-K partials (32-way: sp = c*2 + tcx)
    int g = lane >> 2, tq = lane & 3;
    float* ep = g_epart + (((size_t)(c * 2 + tcx)) * Bsz + b) * Rr * NC1;
    #pragma unroll
    for (int mt = 0; mt < 2; mt++) {
        #pragma unroll
        for (int nt = 0; nt < 8; nt++) {
            int r = wid * 32 + mt * 16 + g;
            int o = nt * 8 + tq * 2;
            *(float2*)(ep + (size_t)r * NC1 + o) = make_float2(acc2[mt][nt][0], acc2[mt][nt][1]);
            *(float2*)(ep + (size_t)(r + 8) * NC1 + o) = make_float2(acc2[mt][nt][2], acc2[mt][nt][3]);
        }
    }
}

// ============================================================
// K3: sum 32 split-K partials, bias + leaky_relu -> e; pooled
// ============================================================
__global__ void k_reduce(const float* __restrict__ b_edge) {
    int br = blockIdx.x;                  // b*R + r
    int b = br >> 8, r = br & 255;
    int o = threadIdx.x;                  // 0..63
    float s = 0.f;
    #pragma unroll 8
    for (int cg = 0; cg < 32; cg++)
        s += g_epart[(((size_t)cg * Bsz + b) * Rr + r) * NC1 + o];
    s += b_edge[o];
    s = (s > 0.f) ? s : 0.01f * s;
    g_e[((size_t)b * Rr + r) * NC1 + o] = s;

    float v = s;
    #pragma unroll
    for (int off = 16; off > 0; off >>= 1) v += __shfl_down_sync(0xffffffffu, v, off);
    __shared__ float w2[2];
    if ((o & 31) == 0) w2[o >> 5] = v;
    __syncthreads();
    if (o == 0) g_pooled[b * Rr + r] = (w2[0] + w2[1]) * (1.0f / 64.0f);
}

// ============================================================
// K4a: per b: MLP attention (parallelized layer-1).  (R14 version)
// ============================================================
__global__ void k_att(const float* __restrict__ W1, const float* __restrict__ b1,
                      const float* __restrict__ W2, const float* __restrict__ b2,
                      float* __restrict__ out) {
    __shared__ __align__(16) float s_p[256];
    __shared__ __align__(16) float s_h[64];
    int b = blockIdx.x, tid = threadIdx.x;

    s_p[tid] = g_pooled[b * Rr + tid];
    __syncthreads();
    {
        int hi = tid >> 2, q = tid & 3;
        const float* w = W1 + hi * 256 + q * 64;
        float a = 0.f;
        #pragma unroll
        for (int j = 0; j < 16; j++) {
            float4 wv = *(const float4*)(w + j * 4);
            float4 pv = *(const float4*)(s_p + q * 64 + j * 4);
            a += wv.x * pv.x + wv.y * pv.y + wv.z * pv.z + wv.w * pv.w;
        }
        a += __shfl_xor_sync(0xffffffffu, a, 1);
        a += __shfl_xor_sync(0xffffffffu, a, 2);
        if (q == 0) {
            a += b1[hi];
            s_h[hi] = a > 0.f ? a : 0.f;
        }
    }
    __syncthreads();
    {
        float a = b2[tid];
        const float* w = W2 + tid * 64;
        #pragma unroll
        for (int j = 0; j < 16; j++) {
            float4 wv = *(const float4*)(w + j * 4);
            float4 hv = *(const float4*)(s_h + j * 4);
            a += wv.x * hv.x + wv.y * hv.y + wv.z * hv.z + wv.w * hv.w;
        }
        float att = 1.0f / (1.0f + expf(-a));
        g_att[b * Rr + tid] = att;
        out[Bsz * NC2 + b * Rr + tid] = att;
    }
}

// ============================================================
// K4b: NodeConv split-K. 64 blocks, each owns 4 r's.  (R14 version)
// ============================================================
__global__ __launch_bounds__(256) void k_node(const float* __restrict__ W_node) {
    __shared__ __align__(16) float sae[32 * 256];       // [b][o][rr]
    __shared__ float s_att[128];
    int blk = blockIdx.x;
    int r0 = blk * 4;
    int tid = threadIdx.x;

    if (tid < 128) {
        int b = tid >> 2, rr = tid & 3;
        s_att[tid] = g_att[b * Rr + r0 + rr];
    }
    __syncthreads();

    #pragma unroll
    for (int i = 0; i < 8; i++) {
        int idx4 = tid + i * 256;
        int b = idx4 >> 6, rr = (idx4 >> 4) & 3, o4 = idx4 & 15;
        float4 v = *(const float4*)(g_e + ((size_t)(b * Rr) + r0 + rr) * NC1 + o4 * 4);
        float a = s_att[b * 4 + rr];
        sae[b * 256 + (o4 * 4 + 0) * 4 + rr] = v.x * a;
        sae[b * 256 + (o4 * 4 + 1) * 4 + rr] = v.y * a;
        sae[b * 256 + (o4 * 4 + 2) * 4 + rr] = v.z * a;
        sae[b * 256 + (o4 * 4 + 3) * 4 + rr] = v.w * a;
    }
    __syncthreads();

    int j = tid >> 1, bh = tid & 1;
    unsigned long long acc2[16];
    #pragma unroll
    for (int i = 0; i < 16; i++) acc2[i] = 0ull;

    const float* wj = W_node + (size_t)j * (NC1 * Rr) + r0;
    #pragma unroll 4
    for (int o = 0; o < 64; o++) {
        ulonglong2 w = *(const ulonglong2*)(wj + o * Rr);
        const float* bsp = sae + bh * 16 * 256 + o * 4;
        #pragma unroll
        for (int bi = 0; bi < 16; bi++) {
            ulonglong2 ae = *(const ulonglong2*)(bsp + bi * 256);
            fma2(acc2[bi], w.x, ae.x);
            fma2(acc2[bi], w.y, ae.y);
        }
    }

    #pragma unroll
    for (int bi = 0; bi < 16; bi++) {
        float2 p = *(float2*)&acc2[bi];
        int b = bh * 16 + bi;
        g_npart[((size_t)blk * 32 + b) * NC2 + j] = p.x + p.y;
    }
}

// ============================================================
// K4c: reduce 64 split-K partials, bias + leaky_relu -> out
// ============================================================
__global__ void k_nred(const float* __restrict__ b_node, float* __restrict__ out) {
    int b = blockIdx.x, j = threadIdx.x;
    float s = 0.f;
    #pragma unroll 8
    for (int sp = 0; sp < 64; sp++)
        s += g_npart[((size_t)sp * 32 + b) * NC2 + j];
    s += b_node[j];
    out[b * NC2 + j] = s > 0.f ? s : 0.01f * s;
}

// ============================================================
extern "C" void kernel_launch(void* const* d_in, const int* in_sizes, int n_in,
                              void* d_out, int out_size) {
    const float* x      = (const float*)d_in[0];
    const float* W_edge = (const float*)d_in[1];
    const float* b_edge = (const float*)d_in[2];
    const float* W1     = (const float*)d_in[3];
    const float* b1     = (const float*)d_in[4];
    const float* W2     = (const float*)d_in[5];
    const float* b2     = (const float*)d_in[6];
    const float* W_node = (const float*)d_in[7];
    const float* b_node = (const float*)d_in[8];
    float* out = (float*)d_out;

    cudaFuncSetAttribute(k_fused, cudaFuncAttributeMaxDynamicSharedMemorySize, FSM_TOTAL);

    k_stats <<<Bsz * Rr, 256>>>(x);
    k_fused <<<Bsz * Cc * 2, 256, FSM_TOTAL>>>(W_edge);
    k_reduce<<<Bsz * Rr, 64>>>(b_edge);
    k_att   <<<Bsz, 256>>>(W1, b1, W2, b2, out);
    k_node  <<<64, 256>>>(W_node);
    k_nred  <<<Bsz, 128>>>(b_node, out);
}

// round 17
// speedup vs baseline: 1.2140x; 1.0300x over previous
#include <cuda_runtime.h>
#include <cuda_bf16.h>
#include <math.h>

#define Bsz 32
#define Rr  256
#define Tt  512
#define Cc  16
#define NC1 64
#define NC2 128

// ---- scratch (static __device__ per allocation rules) ----
__device__ __nv_bfloat16 g_zh[67108864];        // [B*C][R][T] bf16 hi of z
__device__ __nv_bfloat16 g_zl[67108864];        // bf16 lo of z
__device__ float g_epart[8388608];              // [16 c][32 b][256 r][64 o]
__device__ float g_e[524288];                   // [B][R][C1]
__device__ float g_pooled[8192];                // [B][R]
__device__ float g_att[8192];                   // [B][R]
__device__ float g_npart[262144];               // [64 sp][32 b][128 j]

__device__ __forceinline__ void fma2(unsigned long long &d,
                                     unsigned long long a,
                                     unsigned long long b) {
    asm("fma.rn.f32x2 %0, %1, %2, %0;" : "+l"(d) : "l"(a), "l"(b));
}
__device__ __forceinline__ unsigned smem_u32(const void* p) {
    return (unsigned)__cvta_generic_to_shared(p);
}
__device__ __forceinline__ void cp16(unsigned dst, const void* src) {
    asm volatile("cp.async.cg.shared.global [%0], [%1], 16;" :: "r"(dst), "l"(src));
}
#define CP_COMMIT() asm volatile("cp.async.commit_group;")
#define CP_WAIT0()  asm volatile("cp.async.wait_group 0;")
#define CP_WAIT1()  asm volatile("cp.async.wait_group 1;")

// bf16 2-way split of a float pair. hi word: [lo16]=bf16(a), [hi16]=bf16(b).
__device__ __forceinline__ void bf16_split2(float a, float b, unsigned &hi, unsigned &lo) {
    unsigned h;
    asm("cvt.rn.bf16x2.f32 %0, %1, %2;" : "=r"(h) : "f"(b), "f"(a));
    float ha = __uint_as_float(h << 16);
    float hb = __uint_as_float(h & 0xffff0000u);
    unsigned l;
    asm("cvt.rn.bf16x2.f32 %0, %1, %2;" : "=r"(l) : "f"(b - hb), "f"(a - ha));
    hi = h; lo = l;
}

// ---- warp-level tensor core (sm_80+ baseline; works on compute_103) ----
#define LDSM4(r, addr) \
    asm volatile("ldmatrix.sync.aligned.m8n8.x4.shared.b16 {%0,%1,%2,%3}, [%4];" \
        : "=r"((r)[0]), "=r"((r)[1]), "=r"((r)[2]), "=r"((r)[3]) : "r"(addr))

#define LDSM4T(r, addr) \
    asm volatile("ldmatrix.sync.aligned.m8n8.x4.trans.shared.b16 {%0,%1,%2,%3}, [%4];" \
        : "=r"((r)[0]), "=r"((r)[1]), "=r"((r)[2]), "=r"((r)[3]) : "r"(addr))

#define MMA16816(d, a, bp) \
    asm volatile("mma.sync.aligned.m16n8k16.row.col.f32.bf16.bf16.f32 " \
        "{%0,%1,%2,%3}, {%4,%5,%6,%7}, {%8,%9}, {%0,%1,%2,%3};" \
        : "+f"((d)[0]), "+f"((d)[1]), "+f"((d)[2]), "+f"((d)[3]) \
        : "r"((a)[0]), "r"((a)[1]), "r"((a)[2]), "r"((a)[3]), \
          "r"((bp)[0]), "r"((bp)[1]))

// ============================================================
// K1: per (b,r): stats + write z bf16 hi/lo [bc][r][t]
// ============================================================
__global__ void k_stats(const float* __restrict__ x) {
    int br = blockIdx.x;                 // b*R + r
    int b = br >> 8, r = br & 255;
    __shared__ __align__(16) float sx[Cc * 513];
    __shared__ float red[256];
    __shared__ float s_mean[Cc], s_inv[Cc];
    const float* xp = x + (size_t)br * (Tt * Cc);
    int tid = threadIdx.x;

    #pragma unroll
    for (int i = 0; i < 8; i++) {
        int idx4 = tid + i * 256;
        int t = idx4 >> 2;
        int c0 = (idx4 & 3) * 4;
        float4 v = *(const float4*)(xp + idx4 * 4);
        sx[(c0 + 0) * 513 + t] = v.x;
        sx[(c0 + 1) * 513 + t] = v.y;
        sx[(c0 + 2) * 513 + t] = v.z;
        sx[(c0 + 3) * 513 + t] = v.w;
    }
    __syncthreads();

    int c = tid & 15, seg = tid >> 4;
    float p = 0.f;
    #pragma unroll
    for (int u = 0; u < 32; u++) p += sx[c * 513 + seg * 32 + u];
    red[seg * 16 + c] = p;
    __syncthreads();
    if (tid < 16) {
        float s = 0.f;
        #pragma unroll
        for (int sg = 0; sg < 16; sg++) s += red[sg * 16 + tid];
        s_mean[tid] = s * (1.0f / Tt);
    }
    __syncthreads();

    float mc = s_mean[c];
    p = 0.f;
    #pragma unroll
    for (int u = 0; u < 32; u++) {
        float d = sx[c * 513 + seg * 32 + u] - mc;
        p += d * d;
    }
    red[seg * 16 + c] = p;
    __syncthreads();
    if (tid < 16) {
        float s = 0.f;
        #pragma unroll
        for (int sg = 0; sg < 16; sg++) s += red[sg * 16 + tid];
        s_inv[tid] = rsqrtf(s);
    }
    __syncthreads();

    int cw = tid >> 4;
    float m = s_mean[cw], inv = s_inv[cw];
    size_t zoff = (((size_t)b * Cc + cw) * Rr + r) * Tt;
    __nv_bfloat16* zh = g_zh + zoff;
    __nv_bfloat16* zl = g_zl + zoff;
    int q = tid & 15;
    #pragma unroll
    for (int j = 0; j < 8; j++) {
        int t = q * 4 + j * 64;
        float z0 = (sx[cw * 513 + t + 0] - m) * inv;
        float z1 = (sx[cw * 513 + t + 1] - m) * inv;
        float z2 = (sx[cw * 513 + t + 2] - m) * inv;
        float z3 = (sx[cw * 513 + t + 3] - m) * inv;
        unsigned h0, l0, h1, l1;
        bf16_split2(z0, z1, h0, l0);
        bf16_split2(z2, z3, h1, l1);
        uint2 hv; hv.x = h0; hv.y = h1;
        uint2 lv; lv.x = l0; lv.y = l1;
        *(uint2*)(zh + t) = hv;
        *(uint2*)(zl + t) = lv;
    }
}

// ============================================================
// K2 (fused HMMA): per (b,c) CTA, internal t-loop (R14 config).
//  Phase 1: y[64][256] = W * z  -> SMEM (h/l split)
//  Phase 2: epart[r][o] += z * y^T  (16-way split-K over c)
// ============================================================
#define YWS  264
#define YROW 528
#define FSM_WH 0
#define FSM_WL 33792
#define FSM_YH 67584
#define FSM_YL 101376
#define FSM_Z  135168
#define FSM_TOTAL 217088

__global__ __launch_bounds__(256, 1) void k_fused(const float* __restrict__ W_edge) {
    extern __shared__ __align__(16) char fsm[];
    unsigned base = smem_u32(fsm);
    int tid = threadIdx.x;
    int wid = tid >> 5, lane = tid & 31;
    int bc = blockIdx.x;
    int b = bc >> 4, c = bc & 15;
    int mw = wid & 1, nw = wid >> 1;

    // ---- prologue: split W[:,c,:] fp32 -> bf16 hi/lo in smem ----
    {
        __nv_bfloat16* Wh = (__nv_bfloat16*)(fsm + FSM_WH);
        __nv_bfloat16* Wl = (__nv_bfloat16*)(fsm + FSM_WL);
        int wo = tid >> 2, wrs = (tid & 3) * 64;
        const float* wrow = W_edge + (size_t)wo * (Cc * Rr) + (size_t)c * Rr + wrs;
        #pragma unroll
        for (int j = 0; j < 32; j++) {
            float2 v = *(const float2*)(wrow + j * 2);
            unsigned h, l;
            bf16_split2(v.x, v.y, h, l);
            *(unsigned*)(Wh + wo * YWS + wrs + j * 2) = h;
            *(unsigned*)(Wl + wo * YWS + wrs + j * 2) = l;
        }
    }

    const __nv_bfloat16* zh0 = g_zh + (size_t)bc * Rr * Tt;
    const __nv_bfloat16* zl0 = g_zl + (size_t)bc * Rr * Tt;

    int matq = lane >> 3, qr = lane & 7;

    unsigned p1_aoff = (unsigned)(((matq & 1) * 8 + qr) * YROW + (matq >> 1) * 16);
    unsigned awh = base + FSM_WH + (unsigned)(mw * 32) * YROW + p1_aoff;
    unsigned awl = base + FSM_WL + (unsigned)(mw * 32) * YROW + p1_aoff;
    unsigned p1_boff = (unsigned)(((matq & 1) * 8 + qr) * YROW + (nw * 64 + (matq >> 1) * 8) * 2);
    unsigned p2_arow = (unsigned)(((matq & 1) * 8 + qr) * 80 + (matq >> 1) * 16);
    unsigned p2_brow = (unsigned)(((matq >> 1) * 8 + qr) * YROW + (matq & 1) * 16);

    float acc2[2][8][4];
    #pragma unroll
    for (int mt = 0; mt < 2; mt++)
        #pragma unroll
        for (int nt = 0; nt < 8; nt++)
            #pragma unroll
            for (int u = 0; u < 4; u++) acc2[mt][nt][u] = 0.f;

    for (int tc = 0; tc < 2; tc++) {
        int tbase = tc * 256;

        // ================= PHASE 1: y = W * z =================
        auto zfill1 = [&](int kb, int buf) {
            unsigned dh = base + FSM_Z + (unsigned)buf * 33792u;
            unsigned dl = dh + 16896u;
            #pragma unroll
            for (int i = 0; i < 4; i++) {
                int idx = tid + i * 256;
                int row = idx >> 5, seg = idx & 31;
                unsigned doff = (unsigned)(row * YWS + seg * 8) * 2;
                size_t soff = (size_t)(kb * 32 + row) * Tt + tbase + seg * 8;
                cp16(dh + doff, zh0 + soff);
                cp16(dl + doff, zl0 + soff);
            }
            CP_COMMIT();
        };

        float acc1[2][8][4];
        #pragma unroll
        for (int mt = 0; mt < 2; mt++)
            #pragma unroll
            for (int nt = 0; nt < 8; nt++)
                #pragma unroll
                for (int u = 0; u < 4; u++) acc1[mt][nt][u] = 0.f;

        zfill1(0, 0);
        for (int kb = 0; kb < 8; kb++) {
            __syncthreads();
            if (kb + 1 < 8) { zfill1(kb + 1, (kb + 1) & 1); CP_WAIT1(); }
            else CP_WAIT0();
            __syncthreads();

            unsigned zh_b = base + FSM_Z + (unsigned)(kb & 1) * 33792u + p1_boff;
            unsigned zl_b = zh_b + 16896u;
            #pragma unroll
            for (int k0 = 0; k0 < 2; k0++) {
                unsigned akoff = (unsigned)(kb * 32 + k0 * 16) * 2;
                unsigned ah[2][4], al[2][4];
                LDSM4(ah[0], awh + akoff);
                LDSM4(ah[1], awh + (unsigned)(16 * YROW) + akoff);
                LDSM4(al[0], awl + akoff);
                LDSM4(al[1], awl + (unsigned)(16 * YROW) + akoff);
                unsigned zrow = (unsigned)(k0 * 16) * YROW;
                unsigned bh4[4][4], bl4[4][4];
                #pragma unroll
                for (int i = 0; i < 4; i++) {
                    LDSM4T(bh4[i], zh_b + zrow + (unsigned)(i * 16) * 2);
                    LDSM4T(bl4[i], zl_b + zrow + (unsigned)(i * 16) * 2);
                }
                #pragma unroll
                for (int mt = 0; mt < 2; mt++)
                    #pragma unroll
                    for (int i = 0; i < 4; i++)
                        #pragma unroll
                        for (int h = 0; h < 2; h++)
                            MMA16816(acc1[mt][i * 2 + h], ah[mt], &bh4[i][h * 2]);
                #pragma unroll
                for (int mt = 0; mt < 2; mt++)
                    #pragma unroll
                    for (int i = 0; i < 4; i++)
                        #pragma unroll
                        for (int h = 0; h < 2; h++)
                            MMA16816(acc1[mt][i * 2 + h], ah[mt], &bl4[i][h * 2]);
                #pragma unroll
                for (int mt = 0; mt < 2; mt++)
                    #pragma unroll
                    for (int i = 0; i < 4; i++)
                        #pragma unroll
                        for (int h = 0; h < 2; h++)
                            MMA16816(acc1[mt][i * 2 + h], al[mt], &bh4[i][h * 2]);
            }
        }

        // write y (bf16 h/l split) into smem [o][264]
        {
            int g = lane >> 2, tq = lane & 3;
            #pragma unroll
            for (int mt = 0; mt < 2; mt++) {
                #pragma unroll
                for (int nt = 0; nt < 8; nt++) {
                    int o = mw * 32 + mt * 16 + g;
                    int t = nw * 64 + nt * 8 + tq * 2;
                    unsigned h0, l0, h1, l1;
                    bf16_split2(acc1[mt][nt][0], acc1[mt][nt][1], h0, l0);
                    bf16_split2(acc1[mt][nt][2], acc1[mt][nt][3], h1, l1);
                    *(unsigned*)(fsm + FSM_YH + o * YROW + t * 2) = h0;
                    *(unsigned*)(fsm + FSM_YL + o * YROW + t * 2) = l0;
                    *(unsigned*)(fsm + FSM_YH + (o + 8) * YROW + t * 2) = h1;
                    *(unsigned*)(fsm + FSM_YL + (o + 8) * YROW + t * 2) = l1;
                }
            }
        }
        __syncthreads();

        // ================= PHASE 2: epart += z * y^T =================
        auto zfill2 = [&](int ch, int buf) {
            unsigned dh = base + FSM_Z + (unsigned)buf * 40960u;
            unsigned dl = dh + 20480u;
            int r = tid;
            size_t soff = (size_t)r * Tt + tbase + ch * 32;
            #pragma unroll
            for (int j = 0; j < 4; j++) {
                cp16(dh + (unsigned)(r * 80 + j * 16), zh0 + soff + j * 8);
                cp16(dl + (unsigned)(r * 80 + j * 16), zl0 + soff + j * 8);
            }
            CP_COMMIT();
        };

        zfill2(0, 0);
        for (int ch = 0; ch < 8; ch++) {
            __syncthreads();
            if (ch + 1 < 8) { zfill2(ch + 1, (ch + 1) & 1); CP_WAIT1(); }
            else CP_WAIT0();
            __syncthreads();

            unsigned Ah = base + FSM_Z + (unsigned)(ch & 1) * 40960u
                        + (unsigned)(wid * 32) * 80 + p2_arow;
            unsigned Al = Ah + 20480u;
            unsigned Bh = base + FSM_YH + p2_brow + (unsigned)(ch * 64);
            unsigned Bl = base + FSM_YL + p2_brow + (unsigned)(ch * 64);

            #pragma unroll
            for (int k0 = 0; k0 < 2; k0++) {
                unsigned koff = (unsigned)(k0 * 32);
                unsigned ah[2][4], al[2][4];
                LDSM4(ah[0], Ah + koff);
                LDSM4(ah[1], Ah + 16 * 80 + koff);
                LDSM4(al[0], Al + koff);
                LDSM4(al[1], Al + 16 * 80 + koff);
                unsigned bh[4][4], bl[4][4];
                #pragma unroll
                for (int i = 0; i < 4; i++) {
                    LDSM4(bh[i], Bh + (unsigned)(i * 16) * YROW + koff);
                    LDSM4(bl[i], Bl + (unsigned)(i * 16) * YROW + koff);
                }
                #pragma unroll
                for (int mt = 0; mt < 2; mt++)
                    #pragma unroll
                    for (int i = 0; i < 4; i++)
                        #pragma unroll
                        for (int h = 0; h < 2; h++)
                            MMA16816(acc2[mt][i * 2 + h], ah[mt], &bh[i][h * 2]);
                #pragma unroll
                for (int mt = 0; mt < 2; mt++)
                    #pragma unroll
                    for (int i = 0; i < 4; i++)
                        #pragma unroll
                        for (int h = 0; h < 2; h++)
                            MMA16816(acc2[mt][i * 2 + h], ah[mt], &bl[i][h * 2]);
                #pragma unroll
                for (int mt = 0; mt < 2; mt++)
                    #pragma unroll
                    for (int i = 0; i < 4; i++)
                        #pragma unroll
                        for (int h = 0; h < 2; h++)
                            MMA16816(acc2[mt][i * 2 + h], al[mt], &bh[i][h * 2]);
            }
        }
        __syncthreads();
    }

    // epilogue: write split-K partials (16-way over c)
    int g = lane >> 2, tq = lane & 3;
    float* ep = g_epart + ((size_t)c * Bsz + b) * Rr * NC1;
    #pragma unroll
    for (int mt = 0; mt < 2; mt++) {
        #pragma unroll
        for (int nt = 0; nt < 8; nt++) {
            int r = wid * 32 + mt * 16 + g;
            int o = nt * 8 + tq * 2;
            *(float2*)(ep + (size_t)r * NC1 + o) = make_float2(acc2[mt][nt][0], acc2[mt][nt][1]);
            *(float2*)(ep + (size_t)(r + 8) * NC1 + o) = make_float2(acc2[mt][nt][2], acc2[mt][nt][3]);
        }
    }
}

// ============================================================
// K3: sum 16 split-K partials, bias + leaky_relu -> e; pooled
// ============================================================
__global__ void k_reduce(const float* __restrict__ b_edge) {
    int br = blockIdx.x;                  // b*R + r
    int b = br >> 8, r = br & 255;
    int o = threadIdx.x;                  // 0..63
    float s = 0.f;
    #pragma unroll
    for (int cg = 0; cg < 16; cg++)
        s += g_epart[(((size_t)cg * Bsz + b) * Rr + r) * NC1 + o];
    s += b_edge[o];
    s = (s > 0.f) ? s : 0.01f * s;
    g_e[((size_t)b * Rr + r) * NC1 + o] = s;

    float v = s;
    #pragma unroll
    for (int off = 16; off > 0; off >>= 1) v += __shfl_down_sync(0xffffffffu, v, off);
    __shared__ float w2[2];
    if ((o & 31) == 0) w2[o >> 5] = v;
    __syncthreads();
    if (o == 0) g_pooled[b * Rr + r] = (w2[0] + w2[1]) * (1.0f / 64.0f);
}

// ============================================================
// K4a: MLP attention, grid 64 = (b, r-half). Layer-1 recomputed
// per half (16K MACs, trivial); layer-2 covers 128 r per block.
// ============================================================
__global__ void k_att(const float* __restrict__ W1, const float* __restrict__ b1,
                      const float* __restrict__ W2, const float* __restrict__ b2,
                      float* __restrict__ out) {
    __shared__ __align__(16) float s_p[256];
    __shared__ __align__(16) float s_h[64];
    int blk = blockIdx.x;
    int b = blk >> 1, half = blk & 1;
    int tid = threadIdx.x;

    s_p[tid] = g_pooled[b * Rr + tid];
    __syncthreads();
    {
        int hi = tid >> 2, q = tid & 3;
        const float* w = W1 + hi * 256 + q * 64;
        float a = 0.f;
        #pragma unroll
        for (int j = 0; j < 16; j++) {
            float4 wv = *(const float4*)(w + j * 4);
            float4 pv = *(const float4*)(s_p + q * 64 + j * 4);
            a += wv.x * pv.x + wv.y * pv.y + wv.z * pv.z + wv.w * pv.w;
        }
        a += __shfl_xor_sync(0xffffffffu, a, 1);
        a += __shfl_xor_sync(0xffffffffu, a, 2);
        if (q == 0) {
            a += b1[hi];
            s_h[hi] = a > 0.f ? a : 0.f;
        }
    }
    __syncthreads();
    if (tid < 128) {
        int r = half * 128 + tid;
        float a = b2[r];
        const float* w = W2 + r * 64;
        #pragma unroll
        for (int j = 0; j < 16; j++) {
            float4 wv = *(const float4*)(w + j * 4);
            float4 hv = *(const float4*)(s_h + j * 4);
            a += wv.x * hv.x + wv.y * hv.y + wv.z * hv.z + wv.w * hv.w;
        }
        float att = 1.0f / (1.0f + expf(-a));
        g_att[b * Rr + r] = att;
        out[Bsz * NC2 + b * Rr + r] = att;
    }
}

// ============================================================
// K4b: NodeConv split-K. grid 128 = (r-group 64, j-half 2).
// Per thread: j = jh*64 + tid>>2, bh = tid&3 (8 b each).
// ============================================================
__global__ __launch_bounds__(256) void k_node(const float* __restrict__ W_node) {
    __shared__ __align__(16) float sae[32 * 256];       // [b][o][rr]
    __shared__ float s_att[128];
    int blk = blockIdx.x;
    int rgrp = blk >> 1, jh = blk & 1;
    int r0 = rgrp * 4;
    int tid = threadIdx.x;

    if (tid < 128) {
        int b = tid >> 2, rr = tid & 3;
        s_att[tid] = g_att[b * Rr + r0 + rr];
    }
    __syncthreads();

    #pragma unroll
    for (int i = 0; i < 8; i++) {
        int idx4 = tid + i * 256;
        int b = idx4 >> 6, rr = (idx4 >> 4) & 3, o4 = idx4 & 15;
        float4 v = *(const float4*)(g_e + ((size_t)(b * Rr) + r0 + rr) * NC1 + o4 * 4);
        float a = s_att[b * 4 + rr];
        sae[b * 256 + (o4 * 4 + 0) * 4 + rr] = v.x * a;
        sae[b * 256 + (o4 * 4 + 1) * 4 + rr] = v.y * a;
        sae[b * 256 + (o4 * 4 + 2) * 4 + rr] = v.z * a;
        sae[b * 256 + (o4 * 4 + 3) * 4 + rr] = v.w * a;
    }
    __syncthreads();

    int j = jh * 64 + (tid >> 2), bh = tid & 3;   // 8 b per thread
    unsigned long long acc2[8];
    #pragma unroll
    for (int i = 0; i < 8; i++) acc2[i] = 0ull;

    const float* wj = W_node + (size_t)j * (NC1 * Rr) + r0;
    #pragma unroll 4
    for (int o = 0; o < 64; o++) {
        ulonglong2 w = *(const ulonglong2*)(wj + o * Rr);
        const float* bsp = sae + bh * 8 * 256 + o * 4;
        #pragma unroll
        for (int bi = 0; bi < 8; bi++) {
            ulonglong2 ae = *(const ulonglong2*)(bsp + bi * 256);
            fma2(acc2[bi], w.x, ae.x);
            fma2(acc2[bi], w.y, ae.y);
        }
    }

    #pragma unroll
    for (int bi = 0; bi < 8; bi++) {
        float2 p = *(float2*)&acc2[bi];
        int b = bh * 8 + bi;
        g_npart[((size_t)rgrp * 32 + b) * NC2 + j] = p.x + p.y;
    }
}

// ============================================================
// K4c: reduce 64 split-K partials, bias + leaky_relu -> out
// ============================================================
__global__ void k_nred(const float* __restrict__ b_node, float* __restrict__ out) {
    int b = blockIdx.x, j = threadIdx.x;
    float s = 0.f;
    #pragma unroll 8
    for (int sp = 0; sp < 64; sp++)
        s += g_npart[((size_t)sp * 32 + b) * NC2 + j];
    s += b_node[j];
    out[b * NC2 + j] = s > 0.f ? s : 0.01f * s;
}

// ============================================================
extern "C" void kernel_launch(void* const* d_in, const int* in_sizes, int n_in,
                              void* d_out, int out_size) {
    const float* x      = (const float*)d_in[0];
    const float* W_edge = (const float*)d_in[1];
    const float* b_edge = (const float*)d_in[2];
    const float* W1     = (const float*)d_in[3];
    const float* b1     = (const float*)d_in[4];
    const float* W2     = (const float*)d_in[5];
    const float* b2     = (const float*)d_in[6];
    const float* W_node = (const float*)d_in[7];
    const float* b_node = (const float*)d_in[8];
    float* out = (float*)d_out;

    cudaFuncSetAttribute(k_fused, cudaFuncAttributeMaxDynamicSharedMemorySize, FSM_TOTAL);

    k_stats <<<Bsz * Rr, 256>>>(x);
    k_fused <<<Bsz * Cc, 256, FSM_TOTAL>>>(W_edge);
    k_reduce<<<Bsz * Rr, 64>>>(b_edge);
    k_att   <<<Bsz * 2, 256>>>(W1, b1, W2, b2, out);
    k_node  <<<128, 256>>>(W_node);
    k_nred  <<<Bsz, 128>>>(b_node, out);
}